// round 12
// baseline (speedup 1.0000x reference)
#include <cuda_runtime.h>
#include <cuda_fp16.h>

#define NN   100000
#define EE   1600000
#define DINF 67
#define DPAD 72          // padded feature width in halves (9 x uint4)
#define ROWB 144         // bytes per hop-row
#define NRU  36          // half2 pairs per hop-row
#define NG   9           // uint4 groups per hop-row
#define DH   128
#define KTOT 288         // 4 * DPAD halves
#define NSTEP 18         // GEMM k-steps (8 uints each)
#define SCAN_B 1024
#define NBLK   98        // ceil(100000/1024)
#define DEGB  6250       // deg blocks (EE/256)
#define INITB 144        // param-init blocks ((KTOT*DH+255)/256)
#define FB    6250       // fill blocks
#define BB    14063      // bn1 blocks ((NN*NRU+255)/256)
#define ZB    391        // deg-rezero blocks ((NN+255)/256)

// ---------------- scratch (static device memory; no allocs allowed) ----------
__device__ __align__(16) __half g_ubufH[4 * NN * DPAD]; // u0..u3 (scaled domain)
__device__ int    g_degi[NN];               // zero-init at load; re-zeroed per run
__device__ float  g_dis[NN];                // deg^-1/2 (0 for deg 0)
__device__ float  g_rdis[NN];               // deg^+1/2 (0 for deg 0)
__device__ int    g_off[NN + 1];            // CSC offsets
__device__ int    g_cursor[NN];
__device__ int    g_blocksum[NBLK + 1];
__device__ __align__(16) int g_csci[EE];    // CSC source indices (weightless)
__device__ __align__(16) __half g_WcatH[DH * KTOT];  // W1 transposed [o][j]
__device__ float  g_A1[DINF], g_B1[DINF];   // BN1 folded affine
__device__ float  g_A2[DH],   g_B2[DH];     // BN2 + bias1 folded affine
__device__ float  g_y[4][NN];               // layer2 channels (1..3 pre-scaled)
__device__ float  g_ta[NN], g_tb[NN];       // scalar propagation buffers

// ------------- launch 1: degree count + parameter prep (merged) --------------
__global__ void k_deginit(const int* __restrict__ col,
                          const float* __restrict__ g1, const float* __restrict__ b1,
                          const float* __restrict__ m1, const float* __restrict__ v1,
                          const float* __restrict__ W1, const float* __restrict__ bias1,
                          const float* __restrict__ g2, const float* __restrict__ b2,
                          const float* __restrict__ m2, const float* __restrict__ v2) {
    if (blockIdx.x < DEGB) {
        int e = blockIdx.x * blockDim.x + threadIdx.x;
        if (e < EE) atomicAdd(&g_degi[col[e]], 1);
    } else {
        int i = (blockIdx.x - DEGB) * blockDim.x + threadIdx.x;
        if (i < DINF) {
            float s = g1[i] * rsqrtf(v1[i] + 1e-5f);
            g_A1[i] = s;
            g_B1[i] = b1[i] - m1[i] * s;
        }
        if (i < DH) {
            float s = g2[i] * rsqrtf(v2[i] + 1e-5f);
            g_A2[i] = s;
            g_B2[i] = (bias1[i] - m2[i]) * s + b2[i];
        }
        if (i < KTOT * DH) {
            int j = i / DH, o = i - j * DH;
            int hop = j / DPAD, d = j - hop * DPAD;
            float w = (d < DINF) ? W1[(hop * DH + o) * DINF + d] : 0.f;
            g_WcatH[o * KTOT + j] = __float2half_rn(w);   // transposed [o][j]
        }
    }
}

// launch 2: shfl-based block scan -> block-local exclusive offsets + totals
__global__ void k_scanA() {
    __shared__ int ws[32];
    int g = blockIdx.x * SCAN_B + threadIdx.x;
    int lane = threadIdx.x & 31, wid = threadIdx.x >> 5;
    int v = (g < NN) ? g_degi[g] : 0;
    int x = v;
#pragma unroll
    for (int d = 1; d < 32; d <<= 1) {
        int t = __shfl_up_sync(0xFFFFFFFFu, x, d);
        if (lane >= d) x += t;
    }
    if (lane == 31) ws[wid] = x;
    __syncthreads();
    if (wid == 0) {
        int y = ws[lane];
#pragma unroll
        for (int d = 1; d < 32; d <<= 1) {
            int t = __shfl_up_sync(0xFFFFFFFFu, y, d);
            if (lane >= d) y += t;
        }
        ws[lane] = y;
    }
    __syncthreads();
    int incl = x + ((wid > 0) ? ws[wid - 1] : 0);
    if (g < NN) g_off[g] = incl - v;
    if (threadIdx.x == SCAN_B - 1) g_blocksum[blockIdx.x] = incl;
}

// launch 3: finalize offsets + dis/rdis (each block re-scans the 98 sums)
__global__ void k_scanC() {
    __shared__ int s[128];
    int tix = threadIdx.x;
    if (tix < 128) s[tix] = (tix < NBLK) ? g_blocksum[tix] : 0;
    __syncthreads();
#pragma unroll
    for (int d = 1; d < 128; d <<= 1) {
        int t = (tix >= d && tix < 128) ? s[tix - d] : 0;
        __syncthreads();
        if (tix < 128) s[tix] += t;
        __syncthreads();
    }
    int pref = (blockIdx.x == 0) ? 0 : s[blockIdx.x - 1];
    int g = blockIdx.x * SCAN_B + tix;
    if (g < NN) {
        int o = g_off[g] + pref;
        g_off[g] = o;
        g_cursor[g] = o;
        int dg = g_degi[g];
        g_dis[g]  = (dg > 0) ? rsqrtf((float)dg) : 0.f;
        g_rdis[g] = (dg > 0) ? sqrtf((float)dg) : 0.f;
    }
    if (g == 0) g_off[NN] = EE;
}

// launch 4 (profiled slot): CSC fill + bn1->u0 + re-zero g_degi for next run
__global__ void k_fillbn1z(const int* __restrict__ row, const int* __restrict__ col,
                           const float* __restrict__ x) {
    if (blockIdx.x < FB) {
        int e = blockIdx.x * blockDim.x + threadIdx.x;
        if (e < EE) {
            int p = atomicAdd(&g_cursor[col[e]], 1);
            g_csci[p] = row[e];
        }
    } else if (blockIdx.x < FB + BB) {
        int i = (blockIdx.x - FB) * blockDim.x + threadIdx.x;
        if (i >= NN * NRU) return;
        int n = i / NRU, p = i - n * NRU;
        int d = 2 * p;
        float f0 = (d < DINF) ? x[n * DINF + d] * g_A1[d] + g_B1[d] : 0.f;
        float f1 = (d + 1 < DINF) ? x[n * DINF + d + 1] * g_A1[d + 1] + g_B1[d + 1] : 0.f;
        float dis = g_dis[n];
        *reinterpret_cast<__half2*>(g_ubufH + (size_t)n * DPAD + d) =
            __floats2half2_rn(f0 * dis, f1 * dis);
    } else {
        int i = (blockIdx.x - FB - BB) * blockDim.x + threadIdx.x;
        if (i < NN) g_degi[i] = 0;     // after scanC's last read; ready for next run
    }
}

// ---------------- gather hop (weightless HADD2, u-domain only) ----------------
// u_out[c] = dis[c]^2 * sum_{r in N(c)} u_src[r]
__device__ __forceinline__ void edge_add(const char* sbase, int srcn, int c,
                                         __half2* acc) {
    uint4 u = *reinterpret_cast<const uint4*>(sbase + (size_t)srcn * ROWB + c * 16);
    acc[0] = __hadd2(acc[0], *reinterpret_cast<__half2*>(&u.x));
    acc[1] = __hadd2(acc[1], *reinterpret_cast<__half2*>(&u.y));
    acc[2] = __hadd2(acc[2], *reinterpret_cast<__half2*>(&u.z));
    acc[3] = __hadd2(acc[3], *reinterpret_cast<__half2*>(&u.w));
}

__global__ void k_hop(const __half* __restrict__ srcU, __half* __restrict__ dstU) {
    int idx = blockIdx.x * blockDim.x + threadIdx.x;
    if (idx >= NN * NG) return;
    int n = idx / NG, c = idx - n * NG;
    int s = g_off[n], e2 = g_off[n + 1];
    const char* sbase = reinterpret_cast<const char*>(srcU);

    __half2 zero = __floats2half2_rn(0.f, 0.f);
    __half2 A[4][4];
#pragma unroll
    for (int a = 0; a < 4; a++)
#pragma unroll
        for (int k = 0; k < 4; k++) A[a][k] = zero;

    int i = s;
    while (i < e2 && (i & 3)) {                 // peel to 16B-align csci index
        edge_add(sbase, __ldg(&g_csci[i]), c, A[i & 3]);
        i++;
    }
    for (; i + 4 <= e2; i += 4) {               // 4 edges per int4
        int4 p = __ldg(reinterpret_cast<const int4*>(&g_csci[i]));
        edge_add(sbase, p.x, c, A[0]);
        edge_add(sbase, p.y, c, A[1]);
        edge_add(sbase, p.z, c, A[2]);
        edge_add(sbase, p.w, c, A[3]);
    }
    for (; i < e2; i++)                          // tail
        edge_add(sbase, __ldg(&g_csci[i]), c, A[i & 3]);

    float dis = g_dis[n];
    float d2  = dis * dis;
    uint4 uv;
    unsigned* up = reinterpret_cast<unsigned*>(&uv);
#pragma unroll
    for (int k = 0; k < 4; k++) {
        __half2 c0 = __hadd2(A[0][k], A[1][k]);
        __half2 c1 = __hadd2(A[2][k], A[3][k]);
        float2 f0 = __half22float2(c0);
        float2 f1 = __half22float2(c1);
        __half2 u = __floats2half2_rn((f0.x + f1.x) * d2, (f0.y + f1.y) * d2);
        up[k] = *reinterpret_cast<unsigned*>(&u);
    }
    *reinterpret_cast<uint4*>(reinterpret_cast<char*>(dstU) + (size_t)n * ROWB + c * 16) = uv;
}

// ---------------- fp16 tensor-core GEMM on U, rdis-recovery epilogue ----------
__device__ __forceinline__ void cp16(unsigned sdst, const void* gsrc, int sz) {
    asm volatile("cp.async.cg.shared.global [%0], [%1], 16, %2;"
                 :: "r"(sdst), "l"(gsrc), "r"(sz));
}

__global__ void __launch_bounds__(256) k_gemm(const float* __restrict__ W2) {
    __shared__ unsigned As[2][128][8];   // [stage][m][k-uint]
    __shared__ unsigned Bs[2][128][8];   // [stage][n][k-uint]
    __shared__ float W2s[4][128];
    __shared__ float A2s[128], B2s[128];
    __shared__ float Rs[128];            // per-row rdis
    __shared__ float ys[4][128];

    const int bm   = blockIdx.x * 128;
    const int tid  = threadIdx.x;
    const int lane = tid & 31;
    const int warp = tid >> 5;
    const int wm   = (warp & 1) * 64;
    const int wn   = (warp >> 1) * 32;
    const int gr   = lane >> 2;          // 0..7
    const int ct   = lane & 3;           // 0..3

    if (tid < 128) {
        A2s[tid] = g_A2[tid]; B2s[tid] = g_B2[tid];
        int n = bm + tid;
        Rs[tid] = (n < NN) ? g_rdis[n] : 0.f;
    }
#pragma unroll
    for (int l = 0; l < 2; l++) {
        int li = tid + l * 256;
        if (li < 512) {
            W2s[li >> 7][li & 127] = W2[li];
            ys[li >> 7][li & 127] = 0.f;
        }
    }

    float acc[4][4][4];
#pragma unroll
    for (int s = 0; s < 4; s++)
#pragma unroll
        for (int t = 0; t < 4; t++)
#pragma unroll
            for (int r = 0; r < 4; r++) acc[s][t][r] = 0.f;

    const uint4* ub4 = reinterpret_cast<const uint4*>(g_ubufH);
    const uint4* wc4 = reinterpret_cast<const uint4*>(g_WcatH);

    const int mro  = tid >> 1;
    const int gsel = tid & 1;
    const int an   = bm + mro;
    const int asz  = (an < NN) ? 16 : 0;
    const int anc  = (an < NN) ? an : 0;

    auto prefetch = [&](int st, int s) {
        int G = 2 * s + gsel;
        int hop = G / NG, off = G - hop * NG;
        unsigned ad = (unsigned)__cvta_generic_to_shared(&As[st][mro][gsel * 4]);
        cp16(ad, ub4 + (size_t)hop * (NN * NG) + (size_t)anc * NG + off, asz);
        unsigned bd = (unsigned)__cvta_generic_to_shared(&Bs[st][mro][gsel * 4]);
        cp16(bd, wc4 + (size_t)mro * NG * 4 + G, 16);
    };

    prefetch(0, 0);
    asm volatile("cp.async.commit_group;" ::: "memory");

    for (int s = 0; s < NSTEP; s++) {
        int st = s & 1;
        if (s + 1 < NSTEP) {
            prefetch(st ^ 1, s + 1);
            asm volatile("cp.async.commit_group;" ::: "memory");
            asm volatile("cp.async.wait_group 1;" ::: "memory");
        } else {
            asm volatile("cp.async.wait_group 0;" ::: "memory");
        }
        __syncthreads();

        unsigned bf[4][2];
#pragma unroll
        for (int t = 0; t < 4; t++) {
            int col = wn + t * 8 + gr;
            bf[t][0] = Bs[st][col][ct];
            bf[t][1] = Bs[st][col][ct + 4];
        }
#pragma unroll
        for (int si = 0; si < 4; si++) {
            int mrow = wm + si * 16 + gr;
            unsigned a0 = As[st][mrow][ct];
            unsigned a1 = As[st][mrow + 8][ct];
            unsigned a2 = As[st][mrow][ct + 4];
            unsigned a3 = As[st][mrow + 8][ct + 4];
#pragma unroll
            for (int t = 0; t < 4; t++) {
                asm volatile(
                    "mma.sync.aligned.m16n8k16.row.col.f32.f16.f16.f32 "
                    "{%0,%1,%2,%3}, {%4,%5,%6,%7}, {%8,%9}, {%0,%1,%2,%3};"
                    : "+f"(acc[si][t][0]), "+f"(acc[si][t][1]),
                      "+f"(acc[si][t][2]), "+f"(acc[si][t][3])
                    : "r"(a0), "r"(a1), "r"(a2), "r"(a3),
                      "r"(bf[t][0]), "r"(bf[t][1]));
            }
        }
        __syncthreads();
    }

    // epilogue: rdis recovery, BN2+bias1+leaky, W2 projection, smem-reduce
#pragma unroll
    for (int s = 0; s < 4; s++) {
#pragma unroll
        for (int rr = 0; rr < 2; rr++) {
            int m = wm + s * 16 + gr + rr * 8;
            float rm = Rs[m];
            float p0 = 0.f, p1 = 0.f, p2 = 0.f, p3 = 0.f;
#pragma unroll
            for (int t = 0; t < 4; t++) {
#pragma unroll
                for (int cc = 0; cc < 2; cc++) {
                    int o = wn + t * 8 + 2 * ct + cc;
                    int r = rr * 2 + cc;
                    float v = (acc[s][t][r] * rm) * A2s[o] + B2s[o];
                    v = (v > 0.f) ? v : 0.01f * v;
                    p0 += v * W2s[0][o];
                    p1 += v * W2s[1][o];
                    p2 += v * W2s[2][o];
                    p3 += v * W2s[3][o];
                }
            }
            atomicAdd(&ys[0][m], p0);
            atomicAdd(&ys[1][m], p1);
            atomicAdd(&ys[2][m], p2);
            atomicAdd(&ys[3][m], p3);
        }
    }
    __syncthreads();
#pragma unroll
    for (int l = 0; l < 2; l++) {
        int li = tid + l * 256;
        int ch = li >> 7, m = li & 127;
        int n = bm + m;
        if (n < NN) {
            float sc = (ch == 0) ? 1.f : g_dis[n];
            g_y[ch][n] = ys[ch][m] * sc;
        }
    }
}

// deg-0 fixup: exact y for nodes with no in-edges (warp per node; rare/empty)
__global__ void k_fix0(const float* __restrict__ x, const float* __restrict__ W2) {
    int warpg = (blockIdx.x * blockDim.x + threadIdx.x) >> 5;
    int lane = threadIdx.x & 31;
    if (warpg >= NN) return;
    int n = warpg;
    if (g_dis[n] != 0.f) return;            // deg > 0: GEMM result is correct
    float p0 = 0.f, p1 = 0.f, p2 = 0.f, p3 = 0.f;
#pragma unroll
    for (int oo = 0; oo < 4; oo++) {
        int o = lane + 32 * oo;
        float s = 0.f;
        for (int d = 0; d < DINF; d++) {
            float h = x[n * DINF + d] * g_A1[d] + g_B1[d];
            s += h * __half2float(g_WcatH[o * KTOT + d]);   // k=0 block: j = d
        }
        float v = s * g_A2[o] + g_B2[o];
        v = (v > 0.f) ? v : 0.01f * v;
        p0 += v * W2[0 * DH + o];
        p1 += v * W2[1 * DH + o];
        p2 += v * W2[2 * DH + o];
        p3 += v * W2[3 * DH + o];
    }
#pragma unroll
    for (int off = 16; off > 0; off >>= 1) {
        p0 += __shfl_xor_sync(0xFFFFFFFFu, p0, off);
        p1 += __shfl_xor_sync(0xFFFFFFFFu, p1, off);
        p2 += __shfl_xor_sync(0xFFFFFFFFu, p2, off);
        p3 += __shfl_xor_sync(0xFFFFFFFFu, p3, off);
    }
    if (lane == 0) {
        g_y[0][n] = p0;
        g_y[1][n] = 0.f; g_y[2][n] = 0.f; g_y[3][n] = 0.f;  // dis = 0
        (void)p1; (void)p2; (void)p3;
    }
}

// weightless scalar gather: dst[n] = addin[n] (+bias) + scale(n)*sum src[r]
__global__ void k_shop(float* __restrict__ dst, const float* __restrict__ addin,
                       const float* __restrict__ src, const float* __restrict__ bias,
                       int sq) {
    int n = blockIdx.x * blockDim.x + threadIdx.x;
    if (n >= NN) return;
    float acc = 0.f;
    int e2 = g_off[n + 1];
#pragma unroll 4
    for (int i = g_off[n]; i < e2; i++)
        acc += src[__ldg(&g_csci[i])];
    float dis = g_dis[n];
    float sc = sq ? dis * dis : dis;
    dst[n] = addin[n] + (bias ? bias[0] : 0.f) + sc * acc;
}

// ---------------- launch -----------------------------------------------------
extern "C" void kernel_launch(void* const* d_in, const int* in_sizes, int n_in,
                              void* d_out, int out_size) {
    const float* x     = (const float*)d_in[0];
    const int*   ei    = (const int*)  d_in[1];
    const float* g1    = (const float*)d_in[2];
    const float* b1    = (const float*)d_in[3];
    const float* m1    = (const float*)d_in[4];
    const float* v1    = (const float*)d_in[5];
    const float* W1    = (const float*)d_in[6];
    const float* bias1 = (const float*)d_in[7];
    const float* g2    = (const float*)d_in[8];
    const float* b2    = (const float*)d_in[9];
    const float* m2    = (const float*)d_in[10];
    const float* v2    = (const float*)d_in[11];
    const float* W2    = (const float*)d_in[12];
    const float* bias2 = (const float*)d_in[13];
    float* out = (float*)d_out;

    const int* row = ei;
    const int* col = ei + EE;

    const int T = 256;

    // 1: deg + param init   2: scanA   3: scanC   4: fill + bn1-u0 + deg-rezero
    k_deginit<<<DEGB + INITB, T>>>(col, g1, b1, m1, v1, W1, bias1, g2, b2, m2, v2);
    k_scanA<<<NBLK, SCAN_B>>>();
    k_scanC<<<NBLK, SCAN_B>>>();
    k_fillbn1z<<<FB + BB + ZB, T>>>(row, col, x);

    // 5-7: weightless gather hops, u-domain only
    {
        __half* u0;
        cudaGetSymbolAddress((void**)&u0, g_ubufH);
        __half* u1 = u0 + (size_t)NN * DPAD;
        __half* u2 = u1 + (size_t)NN * DPAD;
        __half* u3 = u2 + (size_t)NN * DPAD;
        int blocks = (NN * NG + T - 1) / T;
        k_hop<<<blocks, T>>>(u0, u1);
        k_hop<<<blocks, T>>>(u1, u2);
        k_hop<<<blocks, T>>>(u2, u3);
    }

    // 8: fused fp16 GEMM on U (+ rdis recovery + BN2 + leaky + W2 projection)
    k_gemm<<<(NN + 127) / 128, 256>>>(W2);

    // 9: deg-0 exact fixup (no-op on typical seeds)
    k_fix0<<<(NN * 32 + T - 1) / T, T>>>(x, W2);

    // 10-12: weightless Horner: out = y0 + A(y1 + A(y2 + A y3)) + bias2
    {
        float* ta; float* tb; float* y0;
        cudaGetSymbolAddress((void**)&ta, g_ta);
        cudaGetSymbolAddress((void**)&tb, g_tb);
        cudaGetSymbolAddress((void**)&y0, g_y);
        float* y1 = y0 + NN; float* y2 = y1 + NN; float* y3 = y2 + NN;
        int bn = (NN + T - 1) / T;
        k_shop<<<bn, T>>>(tb, y2, y3, nullptr, 1);
        k_shop<<<bn, T>>>(ta, y1, tb, nullptr, 1);
        k_shop<<<bn, T>>>(out, y0, ta, bias2, 0);
    }
    (void)in_sizes; (void)n_in; (void)out_size;
}

// round 13
// speedup vs baseline: 1.0320x; 1.0320x over previous
#include <cuda_runtime.h>
#include <cuda_fp16.h>

#define NN   100000
#define EE   1600000
#define DINF 67
#define DPAD 72          // padded feature width in halves (9 x uint4)
#define ROWB 144         // bytes per hop-row
#define NRU  36          // half2 pairs per hop-row
#define NG   9           // uint4 groups per hop-row
#define DH   128
#define KTOT 288         // 4 * DPAD halves
#define NSTEP 18         // GEMM k-steps (8 uints each)
#define SCAN_B 1024
#define NBLK   98        // ceil(100000/1024)
#define DEGB  6250       // deg blocks (EE/256)
#define INITB 144        // param-init blocks ((KTOT*DH+255)/256)
#define FB    6250       // fill blocks
#define BB    14063      // bn1 blocks ((NN*NRU+255)/256)
#define ZB    391        // deg-rezero blocks ((NN+255)/256)
#define FXB   13         // fix0 blocks inside shop pass 1

// ---------------- scratch (static device memory; no allocs allowed) ----------
__device__ __align__(16) __half g_ubufH[4 * NN * DPAD]; // u0..u3 (scaled domain)
__device__ int    g_degi[NN];               // zero-init at load; re-zeroed per run
__device__ float  g_dis[NN];                // deg^-1/2 (0 for deg 0)
__device__ float  g_rdis[NN];               // deg^+1/2 (0 for deg 0)
__device__ int    g_off[NN + 1];            // CSC offsets
__device__ int    g_cursor[NN];
__device__ int    g_blocksum[NBLK + 1];
__device__ int    g_n0count;                // number of deg-0 nodes
__device__ int    g_n0list[NN];             // their ids
__device__ __align__(16) int g_csci[EE];    // CSC source indices (weightless)
__device__ __align__(16) __half g_WcatH[DH * KTOT];  // W1 transposed [o][j]
__device__ float  g_A1[DINF], g_B1[DINF];   // BN1 folded affine
__device__ float  g_A2[DH],   g_B2[DH];     // BN2 + bias1 folded affine
__device__ float  g_y[4][NN];               // layer2 channels (1..3 pre-scaled)
__device__ float  g_ta[NN], g_tb[NN];       // scalar propagation buffers

// ------------- launch 1: degree count + parameter prep (merged) --------------
__global__ void k_deginit(const int* __restrict__ col,
                          const float* __restrict__ g1, const float* __restrict__ b1,
                          const float* __restrict__ m1, const float* __restrict__ v1,
                          const float* __restrict__ W1, const float* __restrict__ bias1,
                          const float* __restrict__ g2, const float* __restrict__ b2,
                          const float* __restrict__ m2, const float* __restrict__ v2) {
    if (blockIdx.x < DEGB) {
        int e = blockIdx.x * blockDim.x + threadIdx.x;
        if (e < EE) atomicAdd(&g_degi[col[e]], 1);
    } else {
        int i = (blockIdx.x - DEGB) * blockDim.x + threadIdx.x;
        if (i == 0) g_n0count = 0;          // reset deg-0 list for this replay
        if (i < DINF) {
            float s = g1[i] * rsqrtf(v1[i] + 1e-5f);
            g_A1[i] = s;
            g_B1[i] = b1[i] - m1[i] * s;
        }
        if (i < DH) {
            float s = g2[i] * rsqrtf(v2[i] + 1e-5f);
            g_A2[i] = s;
            g_B2[i] = (bias1[i] - m2[i]) * s + b2[i];
        }
        if (i < KTOT * DH) {
            int j = i / DH, o = i - j * DH;
            int hop = j / DPAD, d = j - hop * DPAD;
            float w = (d < DINF) ? W1[(hop * DH + o) * DINF + d] : 0.f;
            g_WcatH[o * KTOT + j] = __float2half_rn(w);   // transposed [o][j]
        }
    }
}

// launch 2: shfl-based block scan -> block-local exclusive offsets + totals
__global__ void k_scanA() {
    __shared__ int ws[32];
    int g = blockIdx.x * SCAN_B + threadIdx.x;
    int lane = threadIdx.x & 31, wid = threadIdx.x >> 5;
    int v = (g < NN) ? g_degi[g] : 0;
    int x = v;
#pragma unroll
    for (int d = 1; d < 32; d <<= 1) {
        int t = __shfl_up_sync(0xFFFFFFFFu, x, d);
        if (lane >= d) x += t;
    }
    if (lane == 31) ws[wid] = x;
    __syncthreads();
    if (wid == 0) {
        int y = ws[lane];
#pragma unroll
        for (int d = 1; d < 32; d <<= 1) {
            int t = __shfl_up_sync(0xFFFFFFFFu, y, d);
            if (lane >= d) y += t;
        }
        ws[lane] = y;
    }
    __syncthreads();
    int incl = x + ((wid > 0) ? ws[wid - 1] : 0);
    if (g < NN) g_off[g] = incl - v;
    if (threadIdx.x == SCAN_B - 1) g_blocksum[blockIdx.x] = incl;
}

// launch 3: finalize offsets + dis/rdis + deg-0 list
__global__ void k_scanC() {
    __shared__ int s[128];
    int tix = threadIdx.x;
    if (tix < 128) s[tix] = (tix < NBLK) ? g_blocksum[tix] : 0;
    __syncthreads();
#pragma unroll
    for (int d = 1; d < 128; d <<= 1) {
        int t = (tix >= d && tix < 128) ? s[tix - d] : 0;
        __syncthreads();
        if (tix < 128) s[tix] += t;
        __syncthreads();
    }
    int pref = (blockIdx.x == 0) ? 0 : s[blockIdx.x - 1];
    int g = blockIdx.x * SCAN_B + tix;
    if (g < NN) {
        int o = g_off[g] + pref;
        g_off[g] = o;
        g_cursor[g] = o;
        int dg = g_degi[g];
        if (dg > 0) {
            g_dis[g]  = rsqrtf((float)dg);
            g_rdis[g] = sqrtf((float)dg);
        } else {
            g_dis[g] = 0.f;
            g_rdis[g] = 0.f;
            g_n0list[atomicAdd(&g_n0count, 1)] = g;
        }
    }
    if (g == 0) g_off[NN] = EE;
}

// launch 4: CSC fill + bn1->u0 + re-zero g_degi for next replay
__global__ void k_fillbn1z(const int* __restrict__ row, const int* __restrict__ col,
                           const float* __restrict__ x) {
    if (blockIdx.x < FB) {
        int e = blockIdx.x * blockDim.x + threadIdx.x;
        if (e < EE) {
            int p = atomicAdd(&g_cursor[col[e]], 1);
            g_csci[p] = row[e];
        }
    } else if (blockIdx.x < FB + BB) {
        int i = (blockIdx.x - FB) * blockDim.x + threadIdx.x;
        if (i >= NN * NRU) return;
        int n = i / NRU, p = i - n * NRU;
        int d = 2 * p;
        float f0 = (d < DINF) ? x[n * DINF + d] * g_A1[d] + g_B1[d] : 0.f;
        float f1 = (d + 1 < DINF) ? x[n * DINF + d + 1] * g_A1[d + 1] + g_B1[d + 1] : 0.f;
        float dis = g_dis[n];
        *reinterpret_cast<__half2*>(g_ubufH + (size_t)n * DPAD + d) =
            __floats2half2_rn(f0 * dis, f1 * dis);
    } else {
        int i = (blockIdx.x - FB - BB) * blockDim.x + threadIdx.x;
        if (i < NN) g_degi[i] = 0;     // after scanC's last read
    }
}

// ---------------- gather hop (weightless HADD2, u-domain only) ----------------
__device__ __forceinline__ void edge_add(const char* sbase, int srcn, int c,
                                         __half2* acc) {
    uint4 u = *reinterpret_cast<const uint4*>(sbase + (size_t)srcn * ROWB + c * 16);
    acc[0] = __hadd2(acc[0], *reinterpret_cast<__half2*>(&u.x));
    acc[1] = __hadd2(acc[1], *reinterpret_cast<__half2*>(&u.y));
    acc[2] = __hadd2(acc[2], *reinterpret_cast<__half2*>(&u.z));
    acc[3] = __hadd2(acc[3], *reinterpret_cast<__half2*>(&u.w));
}

__global__ void k_hop(const __half* __restrict__ srcU, __half* __restrict__ dstU) {
    int idx = blockIdx.x * blockDim.x + threadIdx.x;
    if (idx >= NN * NG) return;
    int n = idx / NG, c = idx - n * NG;
    int s = g_off[n], e2 = g_off[n + 1];
    const char* sbase = reinterpret_cast<const char*>(srcU);

    __half2 zero = __floats2half2_rn(0.f, 0.f);
    __half2 A[4][4];
#pragma unroll
    for (int a = 0; a < 4; a++)
#pragma unroll
        for (int k = 0; k < 4; k++) A[a][k] = zero;

    int i = s;
    while (i < e2 && (i & 3)) {                 // peel to 16B-align csci index
        edge_add(sbase, __ldg(&g_csci[i]), c, A[i & 3]);
        i++;
    }
    for (; i + 4 <= e2; i += 4) {               // 4 edges per int4
        int4 p = __ldg(reinterpret_cast<const int4*>(&g_csci[i]));
        edge_add(sbase, p.x, c, A[0]);
        edge_add(sbase, p.y, c, A[1]);
        edge_add(sbase, p.z, c, A[2]);
        edge_add(sbase, p.w, c, A[3]);
    }
    for (; i < e2; i++)                          // tail
        edge_add(sbase, __ldg(&g_csci[i]), c, A[i & 3]);

    float dis = g_dis[n];
    float d2  = dis * dis;
    uint4 uv;
    unsigned* up = reinterpret_cast<unsigned*>(&uv);
#pragma unroll
    for (int k = 0; k < 4; k++) {
        __half2 c0 = __hadd2(A[0][k], A[1][k]);
        __half2 c1 = __hadd2(A[2][k], A[3][k]);
        float2 f0 = __half22float2(c0);
        float2 f1 = __half22float2(c1);
        __half2 u = __floats2half2_rn((f0.x + f1.x) * d2, (f0.y + f1.y) * d2);
        up[k] = *reinterpret_cast<unsigned*>(&u);
    }
    *reinterpret_cast<uint4*>(reinterpret_cast<char*>(dstU) + (size_t)n * ROWB + c * 16) = uv;
}

// ---------------- fp16 tensor-core GEMM on U, rdis-recovery epilogue ----------
__device__ __forceinline__ void cp16(unsigned sdst, const void* gsrc, int sz) {
    asm volatile("cp.async.cg.shared.global [%0], [%1], 16, %2;"
                 :: "r"(sdst), "l"(gsrc), "r"(sz));
}

__global__ void __launch_bounds__(256) k_gemm(const float* __restrict__ W2) {
    __shared__ unsigned As[2][128][8];
    __shared__ unsigned Bs[2][128][8];
    __shared__ float W2s[4][128];
    __shared__ float A2s[128], B2s[128];
    __shared__ float Rs[128];
    __shared__ float ys[4][128];

    const int bm   = blockIdx.x * 128;
    const int tid  = threadIdx.x;
    const int lane = tid & 31;
    const int warp = tid >> 5;
    const int wm   = (warp & 1) * 64;
    const int wn   = (warp >> 1) * 32;
    const int gr   = lane >> 2;
    const int ct   = lane & 3;

    if (tid < 128) {
        A2s[tid] = g_A2[tid]; B2s[tid] = g_B2[tid];
        int n = bm + tid;
        Rs[tid] = (n < NN) ? g_rdis[n] : 0.f;
    }
#pragma unroll
    for (int l = 0; l < 2; l++) {
        int li = tid + l * 256;
        if (li < 512) {
            W2s[li >> 7][li & 127] = W2[li];
            ys[li >> 7][li & 127] = 0.f;
        }
    }

    float acc[4][4][4];
#pragma unroll
    for (int s = 0; s < 4; s++)
#pragma unroll
        for (int t = 0; t < 4; t++)
#pragma unroll
            for (int r = 0; r < 4; r++) acc[s][t][r] = 0.f;

    const uint4* ub4 = reinterpret_cast<const uint4*>(g_ubufH);
    const uint4* wc4 = reinterpret_cast<const uint4*>(g_WcatH);

    const int mro  = tid >> 1;
    const int gsel = tid & 1;
    const int an   = bm + mro;
    const int asz  = (an < NN) ? 16 : 0;
    const int anc  = (an < NN) ? an : 0;

    auto prefetch = [&](int st, int s) {
        int G = 2 * s + gsel;
        int hop = G / NG, off = G - hop * NG;
        unsigned ad = (unsigned)__cvta_generic_to_shared(&As[st][mro][gsel * 4]);
        cp16(ad, ub4 + (size_t)hop * (NN * NG) + (size_t)anc * NG + off, asz);
        unsigned bd = (unsigned)__cvta_generic_to_shared(&Bs[st][mro][gsel * 4]);
        cp16(bd, wc4 + (size_t)mro * NG * 4 + G, 16);
    };

    prefetch(0, 0);
    asm volatile("cp.async.commit_group;" ::: "memory");

    for (int s = 0; s < NSTEP; s++) {
        int st = s & 1;
        if (s + 1 < NSTEP) {
            prefetch(st ^ 1, s + 1);
            asm volatile("cp.async.commit_group;" ::: "memory");
            asm volatile("cp.async.wait_group 1;" ::: "memory");
        } else {
            asm volatile("cp.async.wait_group 0;" ::: "memory");
        }
        __syncthreads();

        unsigned bf[4][2];
#pragma unroll
        for (int t = 0; t < 4; t++) {
            int col = wn + t * 8 + gr;
            bf[t][0] = Bs[st][col][ct];
            bf[t][1] = Bs[st][col][ct + 4];
        }
#pragma unroll
        for (int si = 0; si < 4; si++) {
            int mrow = wm + si * 16 + gr;
            unsigned a0 = As[st][mrow][ct];
            unsigned a1 = As[st][mrow + 8][ct];
            unsigned a2 = As[st][mrow][ct + 4];
            unsigned a3 = As[st][mrow + 8][ct + 4];
#pragma unroll
            for (int t = 0; t < 4; t++) {
                asm volatile(
                    "mma.sync.aligned.m16n8k16.row.col.f32.f16.f16.f32 "
                    "{%0,%1,%2,%3}, {%4,%5,%6,%7}, {%8,%9}, {%0,%1,%2,%3};"
                    : "+f"(acc[si][t][0]), "+f"(acc[si][t][1]),
                      "+f"(acc[si][t][2]), "+f"(acc[si][t][3])
                    : "r"(a0), "r"(a1), "r"(a2), "r"(a3),
                      "r"(bf[t][0]), "r"(bf[t][1]));
            }
        }
        __syncthreads();
    }

    // epilogue: rdis recovery, BN2+bias1+leaky, W2 projection, smem-reduce
#pragma unroll
    for (int s = 0; s < 4; s++) {
#pragma unroll
        for (int rr = 0; rr < 2; rr++) {
            int m = wm + s * 16 + gr + rr * 8;
            float rm = Rs[m];
            float p0 = 0.f, p1 = 0.f, p2 = 0.f, p3 = 0.f;
#pragma unroll
            for (int t = 0; t < 4; t++) {
#pragma unroll
                for (int cc = 0; cc < 2; cc++) {
                    int o = wn + t * 8 + 2 * ct + cc;
                    int r = rr * 2 + cc;
                    float v = (acc[s][t][r] * rm) * A2s[o] + B2s[o];
                    v = (v > 0.f) ? v : 0.01f * v;
                    p0 += v * W2s[0][o];
                    p1 += v * W2s[1][o];
                    p2 += v * W2s[2][o];
                    p3 += v * W2s[3][o];
                }
            }
            atomicAdd(&ys[0][m], p0);
            atomicAdd(&ys[1][m], p1);
            atomicAdd(&ys[2][m], p2);
            atomicAdd(&ys[3][m], p3);
        }
    }
    __syncthreads();
#pragma unroll
    for (int l = 0; l < 2; l++) {
        int li = tid + l * 256;
        int ch = li >> 7, m = li & 127;
        int n = bm + m;
        if (n < NN) {
            float sc = (ch == 0) ? 1.f : g_dis[n];
            g_y[ch][n] = ys[ch][m] * sc;
        }
    }
}

// weightless scalar gather body
__device__ __forceinline__ void shop_body(int n, float* __restrict__ dst,
                                          const float* __restrict__ addin,
                                          const float* __restrict__ src,
                                          const float* __restrict__ bias, int sq) {
    float acc = 0.f;
    int e2 = g_off[n + 1];
#pragma unroll 4
    for (int i = g_off[n]; i < e2; i++)
        acc += src[__ldg(&g_csci[i])];
    float dis = g_dis[n];
    float sc = sq ? dis * dis : dis;
    dst[n] = addin[n] + (bias ? bias[0] : 0.f) + sc * acc;
}

// shop pass 1 (tb = y2 + dis^2*S y3) with deg-0 y0 fixup folded in.
// Safe: fixup writes g_y[0] (first read in pass 3); deg-0 y1..3 already 0.
__global__ void k_shop1f(float* __restrict__ tb, const float* __restrict__ x,
                         const float* __restrict__ W2) {
    if (blockIdx.x < FXB) {
        int wg = (blockIdx.x * blockDim.x + threadIdx.x) >> 5;
        int lane = threadIdx.x & 31;
        int nwarps = (FXB * 256) >> 5;
        int cnt = g_n0count;
        for (int li = wg; li < cnt; li += nwarps) {
            int n = g_n0list[li];
            float p0 = 0.f;
#pragma unroll
            for (int oo = 0; oo < 4; oo++) {
                int o = lane + 32 * oo;
                float s = 0.f;
                for (int d = 0; d < DINF; d++) {
                    float h = x[n * DINF + d] * g_A1[d] + g_B1[d];
                    s += h * __half2float(g_WcatH[o * KTOT + d]);   // k=0 block
                }
                float v = s * g_A2[o] + g_B2[o];
                v = (v > 0.f) ? v : 0.01f * v;
                p0 += v * W2[o];
            }
#pragma unroll
            for (int off = 16; off > 0; off >>= 1)
                p0 += __shfl_xor_sync(0xFFFFFFFFu, p0, off);
            if (lane == 0) g_y[0][n] = p0;
        }
    } else {
        int n = (blockIdx.x - FXB) * blockDim.x + threadIdx.x;
        if (n < NN) shop_body(n, tb, g_y[2], g_y[3], nullptr, 1);
    }
}

__global__ void k_shop(float* __restrict__ dst, const float* __restrict__ addin,
                       const float* __restrict__ src, const float* __restrict__ bias,
                       int sq) {
    int n = blockIdx.x * blockDim.x + threadIdx.x;
    if (n < NN) shop_body(n, dst, addin, src, bias, sq);
}

// ---------------- launch -----------------------------------------------------
extern "C" void kernel_launch(void* const* d_in, const int* in_sizes, int n_in,
                              void* d_out, int out_size) {
    const float* x     = (const float*)d_in[0];
    const int*   ei    = (const int*)  d_in[1];
    const float* g1    = (const float*)d_in[2];
    const float* b1    = (const float*)d_in[3];
    const float* m1    = (const float*)d_in[4];
    const float* v1    = (const float*)d_in[5];
    const float* W1    = (const float*)d_in[6];
    const float* bias1 = (const float*)d_in[7];
    const float* g2    = (const float*)d_in[8];
    const float* b2    = (const float*)d_in[9];
    const float* m2    = (const float*)d_in[10];
    const float* v2    = (const float*)d_in[11];
    const float* W2    = (const float*)d_in[12];
    const float* bias2 = (const float*)d_in[13];
    float* out = (float*)d_out;

    const int* row = ei;
    const int* col = ei + EE;

    const int T = 256;

    k_deginit<<<DEGB + INITB, T>>>(col, g1, b1, m1, v1, W1, bias1, g2, b2, m2, v2);
    k_scanA<<<NBLK, SCAN_B>>>();
    k_scanC<<<NBLK, SCAN_B>>>();
    k_fillbn1z<<<FB + BB + ZB, T>>>(row, col, x);

    // weightless gather hops, u-domain only
    {
        __half* u0;
        cudaGetSymbolAddress((void**)&u0, g_ubufH);
        __half* u1 = u0 + (size_t)NN * DPAD;
        __half* u2 = u1 + (size_t)NN * DPAD;
        __half* u3 = u2 + (size_t)NN * DPAD;
        int blocks = (NN * NG + T - 1) / T;
        k_hop<<<blocks, T>>>(u0, u1);
        k_hop<<<blocks, T>>>(u1, u2);
        k_hop<<<blocks, T>>>(u2, u3);
    }

    // fused fp16 GEMM on U (+ rdis recovery + BN2 + leaky + W2 projection)
    k_gemm<<<(NN + 127) / 128, 256>>>(W2);

    // weightless Horner (pass 1 carries the deg-0 fixup)
    {
        float* ta; float* tb; float* y0;
        cudaGetSymbolAddress((void**)&ta, g_ta);
        cudaGetSymbolAddress((void**)&tb, g_tb);
        cudaGetSymbolAddress((void**)&y0, g_y);
        float* y1 = y0 + NN;
        int bn = (NN + T - 1) / T;
        k_shop1f<<<FXB + bn, T>>>(tb, x, W2);
        k_shop<<<bn, T>>>(ta, y1, tb, nullptr, 1);
        k_shop<<<bn, T>>>(out, y0, ta, bias2, 0);
    }
    (void)in_sizes; (void)n_in; (void)out_size;
}